// round 15
// baseline (speedup 1.0000x reference)
#include <cuda_runtime.h>
#include <cstdint>
#include <math.h>

#define EMBED   2048
#define NEXP    64
#define TOPK    8
#define BM      128
#define BK      32
#define NCHUNK  (EMBED / BK)      // 64
#define ABYTES  16384             // A: 128 tokens x 128B
#define STAGE_B 24576             // A 16KB + B 8KB
#define NSTAGE  4
#define SMEM_BYTES (NSTAGE * STAGE_B)   // 98304

typedef unsigned long long ull;

__device__ __forceinline__ uint32_t smem_u32(const void* p) {
    uint32_t a;
    asm("{ .reg .u64 t; cvta.to.shared.u64 t, %1; cvt.u32.u64 %0, t; }" : "=r"(a) : "l"(p));
    return a;
}
// packed dual-fp32 FMA (Blackwell f32x2 pipe, full fp32 per lane)
__device__ __forceinline__ void fma2(ull& c, ull a, ull b) {
    asm("fma.rn.f32x2 %0, %1, %2, %0;" : "+l"(c) : "l"(a), "l"(b));
}
__device__ __forceinline__ void cpa8(uint32_t dst, const void* src) {
    asm volatile("cp.async.ca.shared.global [%0], [%1], 8;" :: "r"(dst), "l"(src));
}
__device__ __forceinline__ float accf(ull v) {   // lo + hi halves
    return __uint_as_float((uint32_t)v) + __uint_as_float((uint32_t)(v >> 32));
}

__global__ __launch_bounds__(256, 2)
void router_f32x2(const float* __restrict__ X,
                  const float* __restrict__ W,
                  const float* __restrict__ bias,
                  float* __restrict__ out,
                  int M, int write_idx)
{
    extern __shared__ float sm[];          // 96 KB: 4 stages; reused for scores
    const uint32_t smb = smem_u32(sm);
    const int tid  = threadIdx.x;
    const int m0   = blockIdx.x * BM;
    const int lane = tid & 31;
    const int tg   = tid >> 5;             // warp: tokens tg*16 .. +15
    const int th   = lane >> 4;            // token half: 8 tokens
    const int eh   = lane & 15;            // expert quad: 4*eh .. 4*eh+3
    const int ueh  = 2 * eh;               // B unit base
    const int rotk = tg * 2 + th;          // A row-rotation key ((token>>3)&7 == (rotk+..)&7)

    // ---- producer addressing ----
    // A: token t row = 128B of 8 16B-units; unit i (k-pairs 2i,2i+1) stored at
    //    t*128 + ((i + (t>>3))&7)*16  — rotation de-conflicts th=0/1 combined loads.
    // B: pair p row = 512B of 32 16B-units; unit u (experts 2u,2u+1) at u^(p&7).
    const int t0 = tid >> 4;               // 0..15
    const int pq = tid & 15;               // k-pair
    const float* xp = X + (size_t)(m0 + t0) * EMBED + pq * 2;
    const float* wp = W + (size_t)t0 * EMBED + pq * 2;
    uint32_t adst[8];
    #pragma unroll
    for (int j = 0; j < 8; j++) {          // token t0+16j  (A region: 2048B per 16 tokens)
        const int t = t0 + 16 * j;
        adst[j] = (uint32_t)(t * 128 + (((pq >> 1) + (t >> 3)) & 7) * 16 + (pq & 1) * 8);
    }
    const uint32_t bdst0 = (uint32_t)(ABYTES + pq * 512
                         + (((t0 >> 1) ^ (pq & 7)) * 16) + (t0 & 1) * 8);

    auto issue = [&](int c) {
        const int k0 = c * BK;
        const uint32_t sb = smb + (uint32_t)(c & 3) * STAGE_B;
        #pragma unroll
        for (int j = 0; j < 8; j++)        // A: tokens t0 + 16j
            cpa8(sb + adst[j], xp + (size_t)j * 16 * EMBED + k0);
        #pragma unroll
        for (int j = 0; j < 4; j++)        // B: experts t0 + 16j (+8 units = 128B)
            cpa8(sb + bdst0 + j * 128u, wp + (size_t)j * 16 * EMBED + k0);
    };

    ull acc[8][4];                         // [token][expert] = (even-k, odd-k) sums
    #pragma unroll
    for (int i = 0; i < 8; i++)
        #pragma unroll
        for (int j = 0; j < 4; j++) acc[i][j] = 0ull;

    issue(0); asm volatile("cp.async.commit_group;");
    issue(1); asm volatile("cp.async.commit_group;");
    issue(2); asm volatile("cp.async.commit_group;");

    for (int c = 0; c < NCHUNK; c++) {
        if (c > 0 && c + 2 < NCHUNK) {     // stage (c+2)&3 free since chunk c-2 (prev barrier)
            issue(c + 2);
            asm volatile("cp.async.commit_group;");
        }
        if (c + 2 < NCHUNK)      asm volatile("cp.async.wait_group 2;");
        else if (c + 1 < NCHUNK) asm volatile("cp.async.wait_group 1;");
        else                     asm volatile("cp.async.wait_group 0;");
        __syncthreads();                   // stage c visible to all warps

        const char* Ab = (const char*)sm + (c & 3) * STAGE_B + tg * 2048 + th * 1024;
        const char* Bb = (const char*)sm + (c & 3) * STAGE_B + ABYTES;
        #pragma unroll
        for (int pp = 0; pp < 8; pp++) {   // 2 k-pairs per step
            const int p0 = 2 * pp, p1 = 2 * pp + 1;
            // B: 4 LDS.128, 16 distinct units x 2 half-warp dup -> 2 wf each, no conflicts
            const ulonglong2 bu0 = *(const ulonglong2*)(Bb + p0 * 512 + (((ueh    ) ^ (p0 & 7)) * 16));
            const ulonglong2 bu1 = *(const ulonglong2*)(Bb + p0 * 512 + (((ueh + 1) ^ (p0 & 7)) * 16));
            const ulonglong2 bu2 = *(const ulonglong2*)(Bb + p1 * 512 + (((ueh    ) ^ (p1 & 7)) * 16));
            const ulonglong2 bu3 = *(const ulonglong2*)(Bb + p1 * 512 + (((ueh + 1) ^ (p1 & 7)) * 16));
            const int ro = ((pp + rotk) & 7) * 16;     // A unit rotation
            #pragma unroll
            for (int tt = 0; tt < 8; tt++) {
                // A: 1 LDS.128, 2 distinct 16B (th=0/1) in different bank quads -> 1 wf
                const ulonglong2 au = *(const ulonglong2*)(Ab + tt * 128 + ro);
                fma2(acc[tt][0], au.x, bu0.x);   // exp 4eh,   pair 2pp
                fma2(acc[tt][1], au.x, bu0.y);   // exp 4eh+1, pair 2pp
                fma2(acc[tt][2], au.x, bu1.x);   // exp 4eh+2, pair 2pp
                fma2(acc[tt][3], au.x, bu1.y);   // exp 4eh+3, pair 2pp
                fma2(acc[tt][0], au.y, bu2.x);   // exp 4eh,   pair 2pp+1
                fma2(acc[tt][1], au.y, bu2.y);
                fma2(acc[tt][2], au.y, bu3.x);
                fma2(acc[tt][3], au.y, bu3.y);
            }
        }
    }
    __syncthreads();                       // all warps done with final stage

    // ---------- stage scores (row stride 68; writes land outside live stage 3) ----------
    #pragma unroll
    for (int tt = 0; tt < 8; tt++) {
        float4 v;
        v.x = accf(acc[tt][0]); v.y = accf(acc[tt][1]);
        v.z = accf(acc[tt][2]); v.w = accf(acc[tt][3]);
        *(float4*)(sm + (tg * 16 + th * 8 + tt) * 68 + eh * 4) = v;
    }
    if (tid < NEXP) sm[8704 + tid] = bias[tid];
    __syncthreads();

    // ---------- per-token top-8 + masked softmax (verified R1/R8-R14) ----------
    if (tid < BM) {
        const int r = tid;
        float sc[64];
        #pragma unroll
        for (int jj = 0; jj < 16; jj++) {
            float4 v  = *(const float4*)(sm + r * 68 + jj * 4);
            float4 bv = *(const float4*)(sm + 8704 + jj * 4);
            sc[jj * 4 + 0] = v.x + bv.x;
            sc[jj * 4 + 1] = v.y + bv.y;
            sc[jj * 4 + 2] = v.z + bv.z;
            sc[jj * 4 + 3] = v.w + bv.w;
        }

        float vals[TOPK];
        int   idxs[TOPK];
        #pragma unroll
        for (int i = 0; i < TOPK; i++) { vals[i] = -INFINITY; idxs[i] = 0; }
        #pragma unroll
        for (int j = 0; j < NEXP; j++) {
            float s = sc[j];
            if (s > vals[TOPK - 1]) {            // strict > : ties keep lower index
                vals[TOPK - 1] = s; idxs[TOPK - 1] = j;
                #pragma unroll
                for (int q = TOPK - 1; q > 0; q--) {
                    if (vals[q] > vals[q - 1]) {
                        float tv = vals[q]; vals[q] = vals[q - 1]; vals[q - 1] = tv;
                        int   ti = idxs[q]; idxs[q] = idxs[q - 1]; idxs[q - 1] = ti;
                    }
                }
            }
        }

        const float mx   = fmaxf(vals[0], 0.f);
        const float base = expf(-mx);
        float den = (float)(NEXP - TOPK) * base;
        float ev[TOPK];
        #pragma unroll
        for (int i = 0; i < TOPK; i++) { ev[i] = expf(vals[i] - mx); den += ev[i]; }
        const float inv = 1.f / den;
        const float bz  = base * inv;

        const int token = m0 + r;
        float* orow = out + (size_t)token * NEXP;
        #pragma unroll
        for (int j = 0; j < NEXP; j += 4) {
            float4 v; v.x = bz; v.y = bz; v.z = bz; v.w = bz;
            *(float4*)(orow + j) = v;
        }
        #pragma unroll
        for (int i = 0; i < TOPK; i++)
            orow[idxs[i]] = ev[i] * inv;

        if (write_idx) {
            float* oi = out + (size_t)M * NEXP + (size_t)token * TOPK;
            #pragma unroll
            for (int i = 0; i < TOPK; i++) oi[i] = (float)idxs[i];
        }
    }
}

extern "C" void kernel_launch(void* const* d_in, const int* in_sizes, int n_in,
                              void* d_out, int out_size) {
    const float* X = (const float*)d_in[0];
    const float* W = (const float*)d_in[1];
    const float* b = (const float*)d_in[2];
    int M = in_sizes[0] / EMBED;                        // 32768 tokens
    int write_idx = (out_size >= M * (NEXP + TOPK)) ? 1 : 0;

    cudaFuncSetAttribute(router_f32x2, cudaFuncAttributeMaxDynamicSharedMemorySize, SMEM_BYTES);
    router_f32x2<<<M / BM, 256, SMEM_BYTES>>>(X, W, b, (float*)d_out, M, write_idx);
}

// round 16
// speedup vs baseline: 1.0259x; 1.0259x over previous
#include <cuda_runtime.h>
#include <cstdint>
#include <math.h>

#define EMBED   2048
#define NEXP    64
#define TOPK    8
#define BM      64
#define BK      32
#define NCHUNK  (EMBED / BK)      // 64
#define STAGE_F 4096              // floats/stage: A 2048 + B 2048 (16 KB)
#define BOFF    2048              // B offset within stage (floats)
#define NSTAGE  6
#define SMEM_BYTES (NSTAGE * STAGE_F * 4)   // 98304 -> occ 2, 296 resident < 512 grid

typedef unsigned long long ull;

__device__ __forceinline__ uint32_t smem_u32(const void* p) {
    uint32_t a;
    asm("{ .reg .u64 t; cvta.to.shared.u64 t, %1; cvt.u32.u64 %0, t; }" : "=r"(a) : "l"(p));
    return a;
}
// packed dual-fp32 FMA (Blackwell f32x2 pipe, full fp32 per lane)
__device__ __forceinline__ void fma2(ull& c, ull a, ull b) {
    asm("fma.rn.f32x2 %0, %1, %2, %0;" : "+l"(c) : "l"(a), "l"(b));
}
__device__ __forceinline__ void cpa8(uint32_t dst, const void* src) {
    asm volatile("cp.async.ca.shared.global [%0], [%1], 8;" :: "r"(dst), "l"(src));
}
__device__ __forceinline__ float accf(ull v) {   // lo + hi halves
    return __uint_as_float((uint32_t)v) + __uint_as_float((uint32_t)(v >> 32));
}

__global__ __launch_bounds__(256, 2)
void router_f32x2(const float* __restrict__ X,
                  const float* __restrict__ W,
                  const float* __restrict__ bias,
                  float* __restrict__ out,
                  int M, int write_idx)
{
    extern __shared__ float sm[];          // 96 KB: 6 stages; reused for scores
    const uint32_t smb = smem_u32(sm);
    const int tid = threadIdx.x;
    const int m0  = blockIdx.x * BM;
    const int tg  = tid >> 5;              // warp: tokens tg*8 .. +7
    const int eg  = tid & 31;              // experts 2*eg, 2*eg+1

    // ---- producer addressing (R12/R13-verified) ----
    // A: [t][k] linear, token row = 32 floats (128B); STS conflict-free
    //    (16 lanes write consecutive 8B within one row).
    // B: [p][e] 16B units, unit u holds experts (2u,2u+1), swizzled u^(p&7);
    //    j-step = +16 experts = +8 units = +128B (XOR commutes, pq&7 < 8).
    const int t0 = tid >> 4;               // 0..15
    const int pq = tid & 15;               // k-pair group
    const float* xp = X + (size_t)(m0 + t0) * EMBED + pq * 2;
    const float* wp = W + (size_t)t0 * EMBED + pq * 2;
    const uint32_t adst0 = (uint32_t)(t0 * 32 + pq * 2) * 4;
    const uint32_t bdst0 = (uint32_t)(BOFF + pq * 128 + (((t0 >> 1) ^ (pq & 7)) * 4) + (t0 & 1) * 2) * 4;

    auto issue = [&](int c) {
        const int k0 = c * BK;
        const uint32_t sb = smb + (uint32_t)(c % NSTAGE) * (STAGE_F * 4);
        #pragma unroll
        for (int j = 0; j < 4; j++)        // A: tokens t0 + 16j
            cpa8(sb + adst0 + j * 2048u, xp + (size_t)j * 16 * EMBED + k0);
        #pragma unroll
        for (int j = 0; j < 4; j++)        // B: experts t0 + 16j (+128B per step)
            cpa8(sb + bdst0 + j * 128u, wp + (size_t)j * 16 * EMBED + k0);
    };

    ull acc[8][2];
    #pragma unroll
    for (int i = 0; i < 8; i++) { acc[i][0] = 0ull; acc[i][1] = 0ull; }

    // prologue: chunks 0..3 in flight (stages 0..3)
    issue(0); asm volatile("cp.async.commit_group;");
    issue(1); asm volatile("cp.async.commit_group;");
    issue(2); asm volatile("cp.async.commit_group;");
    issue(3); asm volatile("cp.async.commit_group;");

    for (int c = 0; c < NCHUNK; c++) {
        // issue(c+4) targets stage (c+4)%6 == (c-2)%6; its reader (chunk c-2)
        // finished before the PREVIOUS iteration's barrier -> safe to overwrite.
        if (c + 4 < NCHUNK) {
            issue(c + 4);
            asm volatile("cp.async.commit_group;");
            asm volatile("cp.async.wait_group 4;");
        }
        else if (c + 3 < NCHUNK) asm volatile("cp.async.wait_group 3;");
        else if (c + 2 < NCHUNK) asm volatile("cp.async.wait_group 2;");
        else if (c + 1 < NCHUNK) asm volatile("cp.async.wait_group 1;");
        else                     asm volatile("cp.async.wait_group 0;");
        __syncthreads();                   // stage c visible to all warps

        const float* Ab = sm + (c % NSTAGE) * STAGE_F + tg * 256;   // warp's 8 token rows
        const float* Bb = sm + (c % NSTAGE) * STAGE_F + BOFF;
        #pragma unroll
        for (int pp = 0; pp < 8; pp++) {   // 2 k-pairs per step
            // B: two conflict-free LDS.128 (lane permutation within 512B row)
            const ulonglong2 bu0 = *(const ulonglong2*)(Bb + (2 * pp)     * 128 + ((eg ^ ((2 * pp)     & 7)) * 4));
            const ulonglong2 bu1 = *(const ulonglong2*)(Bb + (2 * pp + 1) * 128 + ((eg ^ ((2 * pp + 1) & 7)) * 4));
            #pragma unroll
            for (int tt = 0; tt < 8; tt++) {
                // broadcast LDS.128: pairs 2pp (au.x) and 2pp+1 (au.y) of token tt
                const ulonglong2 au = *(const ulonglong2*)(Ab + tt * 32 + pp * 4);
                fma2(acc[tt][0], au.x, bu0.x);   // exp 2eg,   pair 2pp
                fma2(acc[tt][1], au.x, bu0.y);   // exp 2eg+1, pair 2pp
                fma2(acc[tt][0], au.y, bu1.x);   // exp 2eg,   pair 2pp+1
                fma2(acc[tt][1], au.y, bu1.y);   // exp 2eg+1, pair 2pp+1
            }
        }
    }
    __syncthreads();                       // all warps done with final stage

    // ---------- stage scores (row stride 68; region [0,4416) is dead stage data) ----------
    #pragma unroll
    for (int tt = 0; tt < 8; tt++) {
        float2 v;
        v.x = accf(acc[tt][0]);            // expert 2*eg
        v.y = accf(acc[tt][1]);            // expert 2*eg+1
        *(float2*)(sm + (tg * 8 + tt) * 68 + eg * 2) = v;
    }
    if (tid < NEXP) sm[4400 + tid] = bias[tid];
    __syncthreads();

    // ---------- per-token top-8 + masked softmax (verified R1/R8-R15) ----------
    if (tid < BM) {
        const int r = tid;
        float sc[64];
        #pragma unroll
        for (int jj = 0; jj < 16; jj++) {
            float4 v  = *(const float4*)(sm + r * 68 + jj * 4);
            float4 bv = *(const float4*)(sm + 4400 + jj * 4);
            sc[jj * 4 + 0] = v.x + bv.x;
            sc[jj * 4 + 1] = v.y + bv.y;
            sc[jj * 4 + 2] = v.z + bv.z;
            sc[jj * 4 + 3] = v.w + bv.w;
        }

        float vals[TOPK];
        int   idxs[TOPK];
        #pragma unroll
        for (int i = 0; i < TOPK; i++) { vals[i] = -INFINITY; idxs[i] = 0; }
        #pragma unroll
        for (int j = 0; j < NEXP; j++) {
            float s = sc[j];
            if (s > vals[TOPK - 1]) {            // strict > : ties keep lower index
                vals[TOPK - 1] = s; idxs[TOPK - 1] = j;
                #pragma unroll
                for (int q = TOPK - 1; q > 0; q--) {
                    if (vals[q] > vals[q - 1]) {
                        float tv = vals[q]; vals[q] = vals[q - 1]; vals[q - 1] = tv;
                        int   ti = idxs[q]; idxs[q] = idxs[q - 1]; idxs[q - 1] = ti;
                    }
                }
            }
        }

        const float mx   = fmaxf(vals[0], 0.f);
        const float base = expf(-mx);
        float den = (float)(NEXP - TOPK) * base;
        float ev[TOPK];
        #pragma unroll
        for (int i = 0; i < TOPK; i++) { ev[i] = expf(vals[i] - mx); den += ev[i]; }
        const float inv = 1.f / den;
        const float bz  = base * inv;

        const int token = m0 + r;
        float* orow = out + (size_t)token * NEXP;
        #pragma unroll
        for (int j = 0; j < NEXP; j += 4) {
            float4 v; v.x = bz; v.y = bz; v.z = bz; v.w = bz;
            *(float4*)(orow + j) = v;
        }
        #pragma unroll
        for (int i = 0; i < TOPK; i++)
            orow[idxs[i]] = ev[i] * inv;

        if (write_idx) {
            float* oi = out + (size_t)M * NEXP + (size_t)token * TOPK;
            #pragma unroll
            for (int i = 0; i < TOPK; i++) oi[i] = (float)idxs[i];
        }
    }
}

extern "C" void kernel_launch(void* const* d_in, const int* in_sizes, int n_in,
                              void* d_out, int out_size) {
    const float* X = (const float*)d_in[0];
    const float* W = (const float*)d_in[1];
    const float* b = (const float*)d_in[2];
    int M = in_sizes[0] / EMBED;                        // 32768 tokens
    int write_idx = (out_size >= M * (NEXP + TOPK)) ? 1 : 0;

    cudaFuncSetAttribute(router_f32x2, cudaFuncAttributeMaxDynamicSharedMemorySize, SMEM_BYTES);
    router_f32x2<<<M / BM, 256, SMEM_BYTES>>>(X, W, b, (float*)d_out, M, write_idx);
}